// round 11
// baseline (speedup 1.0000x reference)
#include <cuda_runtime.h>
#include <math.h>

#define TT 4096
#define II 512
#define HH 1024
#define OO 256

#define REC_GRID 128
#define REC_THREADS 256   // 8 warps; warp w owns hidden unit blockIdx.x*8+w
#define UNITS_PER_CTA 8

// Scratch (allocation-free: __device__ globals)
__device__ float g_gx[4][TT][HH];        // per-gate input projections
__device__ float g_h[(TT + 1) * HH];     // row 0 = h_{-1} = 0, row t+1 = h_t
__device__ unsigned g_bar;               // grid barrier counter (monotonic per launch)

// ---------------------------------------------------------------------------
__global__ void init_kernel() {
    int i = blockIdx.x * blockDim.x + threadIdx.x;
    if (i < HH) g_h[i] = 0.0f;
    if (i == 0) g_bar = 0u;
}

// ---------------------------------------------------------------------------
// C[M,N] = A[M,K] @ B[N,K]^T + bias[N]   (both A and B are K-contiguous)
// ---------------------------------------------------------------------------
__global__ __launch_bounds__(256) void gemm_tn_bias(
    const float* __restrict__ A, const float* __restrict__ B,
    const float* __restrict__ bias, float* __restrict__ C,
    int M, int N, int K)
{
    __shared__ float As[16][68];
    __shared__ float Bs[16][68];

    const int bm = blockIdx.y * 64;
    const int bn = blockIdx.x * 64;
    const int tid = threadIdx.x;

    const int lr = tid >> 2;
    const int lk = (tid & 3) << 2;
    const int tx = tid & 15;
    const int ty = tid >> 4;

    float acc[4][4] = {};

    for (int k0 = 0; k0 < K; k0 += 16) {
        float4 av = *(const float4*)(A + (size_t)(bm + lr) * K + k0 + lk);
        float4 bv = *(const float4*)(B + (size_t)(bn + lr) * K + k0 + lk);
        __syncthreads();
        As[lk + 0][lr] = av.x; As[lk + 1][lr] = av.y;
        As[lk + 2][lr] = av.z; As[lk + 3][lr] = av.w;
        Bs[lk + 0][lr] = bv.x; Bs[lk + 1][lr] = bv.y;
        Bs[lk + 2][lr] = bv.z; Bs[lk + 3][lr] = bv.w;
        __syncthreads();
#pragma unroll
        for (int kk = 0; kk < 16; kk++) {
            float4 af = *(const float4*)&As[kk][ty * 4];
            float4 bf = *(const float4*)&Bs[kk][tx * 4];
            float am[4] = {af.x, af.y, af.z, af.w};
            float bn_[4] = {bf.x, bf.y, bf.z, bf.w};
#pragma unroll
            for (int i = 0; i < 4; i++)
#pragma unroll
                for (int j = 0; j < 4; j++)
                    acc[i][j] += am[i] * bn_[j];
        }
    }

    const int row = bm + ty * 4;
    const int col = bn + tx * 4;
    float b0 = bias[col + 0], b1 = bias[col + 1], b2 = bias[col + 2], b3 = bias[col + 3];
#pragma unroll
    for (int i = 0; i < 4; i++) {
        float4 out;
        out.x = acc[i][0] + b0;
        out.y = acc[i][1] + b1;
        out.z = acc[i][2] + b2;
        out.w = acc[i][3] + b3;
        *(float4*)&C[(size_t)(row + i) * N + col] = out;
    }
}

__device__ __forceinline__ float fast_sigmoid(float x) {
    return 0.5f * __tanhf(0.5f * x) + 0.5f;   // one MUFU, no divide
}

// packed f32x2 fma: acc = a*b + acc (elementwise on 2 packed floats)
__device__ __forceinline__ void fma_f32x2(unsigned long long& acc,
                                          unsigned long long a,
                                          unsigned long long b) {
    asm("fma.rn.f32x2 %0, %1, %2, %0;" : "+l"(acc) : "l"(a), "l"(b));
}

// ---------------------------------------------------------------------------
// Persistent recurrence. 128 CTAs, 8 warps each; warp w owns unit b*8+w.
// Dot product uses packed f32x2 FMA (FFMA2): 64 packed ops vs 128 scalar.
// Barrier (r10-proven): __syncthreads -> red.release.gpu.add by thread 0 ->
// acquire-polls (ordering carried by the poll loads; no extra confirm trip).
// ---------------------------------------------------------------------------
__global__ __launch_bounds__(REC_THREADS, 1) void lstm_rec(
    const float* __restrict__ Whf, const float* __restrict__ Whi,
    const float* __restrict__ Whc, const float* __restrict__ Who)
{
    const int w = threadIdx.x >> 5;
    const int l = threadIdx.x & 31;
    const int unit = blockIdx.x * UNITS_PER_CTA + w;

    // Recurrent weights in registers as packed f32x2 pairs.
    // Chunk i covers h[l*4 + 128*i .. +4): pairs (0,1) and (2,3).
    unsigned long long wf[16], wi[16], wc[16], wo[16];
    {
        const float* rf = Whf + (size_t)unit * HH;
        const float* ri = Whi + (size_t)unit * HH;
        const float* rc = Whc + (size_t)unit * HH;
        const float* ro = Who + (size_t)unit * HH;
#pragma unroll
        for (int i = 0; i < 8; i++) {
            int c = l * 4 + 128 * i;
            ulonglong2 vf = *(const ulonglong2*)(rf + c);
            ulonglong2 vi = *(const ulonglong2*)(ri + c);
            ulonglong2 vc = *(const ulonglong2*)(rc + c);
            ulonglong2 vo = *(const ulonglong2*)(ro + c);
            wf[2*i] = vf.x; wf[2*i+1] = vf.y;
            wi[2*i] = vi.x; wi[2*i+1] = vi.y;
            wc[2*i] = vc.x; wc[2*i+1] = vc.y;
            wo[2*i] = vo.x; wo[2*i+1] = vo.y;
        }
    }

    float cst = 0.0f;  // cell state (lane 0)

    // Prefetch gx for t=0
    float gxf = 0.f, gxi = 0.f, gxc = 0.f, gxo = 0.f;
    if (l == 0) {
        gxf = __ldcg(&g_gx[0][0][unit]);
        gxi = __ldcg(&g_gx[1][0][unit]);
        gxc = __ldcg(&g_gx[2][0][unit]);
        gxo = __ldcg(&g_gx[3][0][unit]);
    }

    for (int t = 0; t < TT; t++) {
        const float* hrow = g_h + (size_t)t * HH;

        unsigned long long pf = 0, pi = 0, pc = 0, po = 0;  // packed (0.0f,0.0f)
#pragma unroll
        for (int i = 0; i < 8; i++) {
            const float* p = hrow + l * 4 + 128 * i;
            unsigned long long h0, h1;   // packed pairs (x,y) and (z,w)
            asm volatile("ld.global.cg.v2.u64 {%0, %1}, [%2];"
                         : "=l"(h0), "=l"(h1) : "l"(p) : "memory");
            fma_f32x2(pf, wf[2*i], h0); fma_f32x2(pf, wf[2*i+1], h1);
            fma_f32x2(pi, wi[2*i], h0); fma_f32x2(pi, wi[2*i+1], h1);
            fma_f32x2(pc, wc[2*i], h0); fma_f32x2(pc, wc[2*i+1], h1);
            fma_f32x2(po, wo[2*i], h0); fma_f32x2(po, wo[2*i+1], h1);
        }

        // unpack + horizontal add: gate partial per lane
        float af, ai, ac, ao;
        {
            float lo, hi;
            asm("mov.b64 {%0,%1}, %2;" : "=f"(lo), "=f"(hi) : "l"(pf)); af = lo + hi;
            asm("mov.b64 {%0,%1}, %2;" : "=f"(lo), "=f"(hi) : "l"(pi)); ai = lo + hi;
            asm("mov.b64 {%0,%1}, %2;" : "=f"(lo), "=f"(hi) : "l"(pc)); ac = lo + hi;
            asm("mov.b64 {%0,%1}, %2;" : "=f"(lo), "=f"(hi) : "l"(po)); ao = lo + hi;
        }
#pragma unroll
        for (int off = 16; off > 0; off >>= 1) {
            af += __shfl_xor_sync(0xffffffffu, af, off);
            ai += __shfl_xor_sync(0xffffffffu, ai, off);
            ac += __shfl_xor_sync(0xffffffffu, ac, off);
            ao += __shfl_xor_sync(0xffffffffu, ao, off);
        }

        if (l == 0) {
            float f_ = fast_sigmoid(af + gxf);
            float i_ = fast_sigmoid(ai + gxi);
            float cd = __tanhf(ac + gxc);
            float o_ = fast_sigmoid(ao + gxo);
            cst = f_ * cst + i_ * cd;
            float h_ = o_ * cst;                   // reference omits tanh(c)
            __stcg(&g_h[(size_t)(t + 1) * HH + unit], h_);

            // prefetch gx for next step (overlaps barrier + next dot)
            int tn = (t + 1 < TT) ? (t + 1) : t;
            gxf = __ldcg(&g_gx[0][tn][unit]);
            gxi = __ldcg(&g_gx[1][tn][unit]);
            gxc = __ldcg(&g_gx[2][tn][unit]);
            gxo = __ldcg(&g_gx[3][tn][unit]);
        }

        // ---- grid barrier: release RED + acquire polls (no confirm trip) ----
        __syncthreads();                           // CTA h stores done
        if (threadIdx.x == 0) {
            asm volatile("red.release.gpu.global.add.u32 [%0], %1;"
                         :: "l"(&g_bar), "r"(1u) : "memory");
            unsigned tgt = (unsigned)(t + 1) * (unsigned)REC_GRID;
            unsigned v;
            do {
                asm volatile("ld.acquire.gpu.global.u32 %0, [%1];"
                             : "=r"(v) : "l"(&g_bar) : "memory");
            } while (v < tgt);
        }
        __syncthreads();
    }
}

// ---------------------------------------------------------------------------
extern "C" void kernel_launch(void* const* d_in, const int* in_sizes, int n_in,
                              void* d_out, int out_size)
{
    const float* x   = (const float*)d_in[0];
    const float* Wxf = (const float*)d_in[1];
    const float* Whf = (const float*)d_in[2];
    const float* bf  = (const float*)d_in[3];
    const float* Wxi = (const float*)d_in[4];
    const float* Whi = (const float*)d_in[5];
    const float* bi  = (const float*)d_in[6];
    const float* Wxc = (const float*)d_in[7];
    const float* Whc = (const float*)d_in[8];
    const float* bc  = (const float*)d_in[9];
    const float* Wxo = (const float*)d_in[10];
    const float* Who = (const float*)d_in[11];
    const float* bo  = (const float*)d_in[12];
    const float* Wy  = (const float*)d_in[13];
    const float* by  = (const float*)d_in[14];
    float* y = (float*)d_out;

    void* p_gx = nullptr;
    void* p_h  = nullptr;
    cudaGetSymbolAddress(&p_gx, g_gx);
    cudaGetSymbolAddress(&p_h,  g_h);
    float* gx = (float*)p_gx;
    float* hbuf = (float*)p_h;

    init_kernel<<<4, 256>>>();

    // Input projections: 4 GEMMs [4096,1024] = x[4096,512] @ Wx^T + b
    dim3 g1(HH / 64, TT / 64);
    gemm_tn_bias<<<g1, 256>>>(x, Wxf, bf, gx + 0 * (size_t)TT * HH, TT, HH, II);
    gemm_tn_bias<<<g1, 256>>>(x, Wxi, bi, gx + 1 * (size_t)TT * HH, TT, HH, II);
    gemm_tn_bias<<<g1, 256>>>(x, Wxc, bc, gx + 2 * (size_t)TT * HH, TT, HH, II);
    gemm_tn_bias<<<g1, 256>>>(x, Wxo, bo, gx + 3 * (size_t)TT * HH, TT, HH, II);

    // Sequential recurrence (persistent, weights in registers)
    lstm_rec<<<REC_GRID, REC_THREADS>>>(Whf, Whi, Whc, Who);

    // Output projection: y[4096,256] = hs[4096,1024] @ Wy^T + by
    dim3 g2(OO / 64, TT / 64);
    gemm_tn_bias<<<g2, 256>>>(hbuf + HH, Wy, by, y, TT, OO, HH);
}

// round 12
// speedup vs baseline: 1.0247x; 1.0247x over previous
#include <cuda_runtime.h>
#include <math.h>

#define TT 4096
#define II 512
#define HH 1024
#define OO 256

#define REC_GRID 128
#define REC_THREADS 256   // 8 warps; warp w owns hidden unit blockIdx.x*8+w
#define UNITS_PER_CTA 8

// Scratch (allocation-free: __device__ globals)
__device__ float g_gx[4][TT][HH];        // per-gate input projections
__device__ float g_h[(TT + 1) * HH];     // row 0 = h_{-1} = 0, row t+1 = h_t
__device__ unsigned g_bar;               // grid barrier counter (monotonic per launch)

// ---------------------------------------------------------------------------
__global__ void init_kernel() {
    int i = blockIdx.x * blockDim.x + threadIdx.x;
    if (i < HH) g_h[i] = 0.0f;
    if (i == 0) g_bar = 0u;
}

// ---------------------------------------------------------------------------
// C[M,N] = A[M,K] @ B[N,K]^T + bias[N]   (both A and B are K-contiguous)
// ---------------------------------------------------------------------------
__global__ __launch_bounds__(256) void gemm_tn_bias(
    const float* __restrict__ A, const float* __restrict__ B,
    const float* __restrict__ bias, float* __restrict__ C,
    int M, int N, int K)
{
    __shared__ float As[16][68];
    __shared__ float Bs[16][68];

    const int bm = blockIdx.y * 64;
    const int bn = blockIdx.x * 64;
    const int tid = threadIdx.x;

    const int lr = tid >> 2;
    const int lk = (tid & 3) << 2;
    const int tx = tid & 15;
    const int ty = tid >> 4;

    float acc[4][4] = {};

    for (int k0 = 0; k0 < K; k0 += 16) {
        float4 av = *(const float4*)(A + (size_t)(bm + lr) * K + k0 + lk);
        float4 bv = *(const float4*)(B + (size_t)(bn + lr) * K + k0 + lk);
        __syncthreads();
        As[lk + 0][lr] = av.x; As[lk + 1][lr] = av.y;
        As[lk + 2][lr] = av.z; As[lk + 3][lr] = av.w;
        Bs[lk + 0][lr] = bv.x; Bs[lk + 1][lr] = bv.y;
        Bs[lk + 2][lr] = bv.z; Bs[lk + 3][lr] = bv.w;
        __syncthreads();
#pragma unroll
        for (int kk = 0; kk < 16; kk++) {
            float4 af = *(const float4*)&As[kk][ty * 4];
            float4 bf = *(const float4*)&Bs[kk][tx * 4];
            float am[4] = {af.x, af.y, af.z, af.w};
            float bn_[4] = {bf.x, bf.y, bf.z, bf.w};
#pragma unroll
            for (int i = 0; i < 4; i++)
#pragma unroll
                for (int j = 0; j < 4; j++)
                    acc[i][j] += am[i] * bn_[j];
        }
    }

    const int row = bm + ty * 4;
    const int col = bn + tx * 4;
    float b0 = bias[col + 0], b1 = bias[col + 1], b2 = bias[col + 2], b3 = bias[col + 3];
#pragma unroll
    for (int i = 0; i < 4; i++) {
        float4 out;
        out.x = acc[i][0] + b0;
        out.y = acc[i][1] + b1;
        out.z = acc[i][2] + b2;
        out.w = acc[i][3] + b3;
        *(float4*)&C[(size_t)(row + i) * N + col] = out;
    }
}

__device__ __forceinline__ float fast_sigmoid(float x) {
    return 0.5f * __tanhf(0.5f * x) + 0.5f;   // one MUFU, no divide
}

// packed f32x2 fma: acc = a*b + acc (elementwise on 2 packed floats)
__device__ __forceinline__ void fma_f32x2(unsigned long long& acc,
                                          unsigned long long a,
                                          unsigned long long b) {
    asm("fma.rn.f32x2 %0, %1, %2, %0;" : "+l"(acc) : "l"(a), "l"(b));
}

// ---------------------------------------------------------------------------
// Persistent recurrence. 128 CTAs, 8 warps each; warp w owns unit b*8+w.
// Dot product: packed f32x2 FMA (FFMA2) — 64 packed ops vs 128 scalar.
// Barrier: EXACTLY r10's proven one — __syncthreads -> red.release.gpu.add by
// thread 0 -> RELAXED polls -> one ld.acquire confirm -> __syncthreads.
// ---------------------------------------------------------------------------
__global__ __launch_bounds__(REC_THREADS, 1) void lstm_rec(
    const float* __restrict__ Whf, const float* __restrict__ Whi,
    const float* __restrict__ Whc, const float* __restrict__ Who)
{
    const int w = threadIdx.x >> 5;
    const int l = threadIdx.x & 31;
    const int unit = blockIdx.x * UNITS_PER_CTA + w;

    // Recurrent weights in registers as packed f32x2 pairs.
    // Chunk i covers h[l*4 + 128*i .. +4): pairs (0,1) and (2,3).
    unsigned long long wf[16], wi[16], wc[16], wo[16];
    {
        const float* rf = Whf + (size_t)unit * HH;
        const float* ri = Whi + (size_t)unit * HH;
        const float* rc = Whc + (size_t)unit * HH;
        const float* ro = Who + (size_t)unit * HH;
#pragma unroll
        for (int i = 0; i < 8; i++) {
            int c = l * 4 + 128 * i;
            ulonglong2 vf = *(const ulonglong2*)(rf + c);
            ulonglong2 vi = *(const ulonglong2*)(ri + c);
            ulonglong2 vc = *(const ulonglong2*)(rc + c);
            ulonglong2 vo = *(const ulonglong2*)(ro + c);
            wf[2*i] = vf.x; wf[2*i+1] = vf.y;
            wi[2*i] = vi.x; wi[2*i+1] = vi.y;
            wc[2*i] = vc.x; wc[2*i+1] = vc.y;
            wo[2*i] = vo.x; wo[2*i+1] = vo.y;
        }
    }

    float cst = 0.0f;  // cell state (lane 0)

    // Prefetch gx for t=0
    float gxf = 0.f, gxi = 0.f, gxc = 0.f, gxo = 0.f;
    if (l == 0) {
        gxf = __ldcg(&g_gx[0][0][unit]);
        gxi = __ldcg(&g_gx[1][0][unit]);
        gxc = __ldcg(&g_gx[2][0][unit]);
        gxo = __ldcg(&g_gx[3][0][unit]);
    }

    for (int t = 0; t < TT; t++) {
        const float* hrow = g_h + (size_t)t * HH;

        unsigned long long pf = 0, pi = 0, pc = 0, po = 0;  // packed (0.0f,0.0f)
#pragma unroll
        for (int i = 0; i < 8; i++) {
            const float* p = hrow + l * 4 + 128 * i;
            unsigned long long h0, h1;   // packed pairs (x,y) and (z,w)
            asm volatile("ld.global.cg.v2.u64 {%0, %1}, [%2];"
                         : "=l"(h0), "=l"(h1) : "l"(p) : "memory");
            fma_f32x2(pf, wf[2*i], h0); fma_f32x2(pf, wf[2*i+1], h1);
            fma_f32x2(pi, wi[2*i], h0); fma_f32x2(pi, wi[2*i+1], h1);
            fma_f32x2(pc, wc[2*i], h0); fma_f32x2(pc, wc[2*i+1], h1);
            fma_f32x2(po, wo[2*i], h0); fma_f32x2(po, wo[2*i+1], h1);
        }

        // unpack + horizontal add: gate partial per lane
        float af, ai, ac, ao;
        {
            float lo, hi;
            asm("mov.b64 {%0,%1}, %2;" : "=f"(lo), "=f"(hi) : "l"(pf)); af = lo + hi;
            asm("mov.b64 {%0,%1}, %2;" : "=f"(lo), "=f"(hi) : "l"(pi)); ai = lo + hi;
            asm("mov.b64 {%0,%1}, %2;" : "=f"(lo), "=f"(hi) : "l"(pc)); ac = lo + hi;
            asm("mov.b64 {%0,%1}, %2;" : "=f"(lo), "=f"(hi) : "l"(po)); ao = lo + hi;
        }
#pragma unroll
        for (int off = 16; off > 0; off >>= 1) {
            af += __shfl_xor_sync(0xffffffffu, af, off);
            ai += __shfl_xor_sync(0xffffffffu, ai, off);
            ac += __shfl_xor_sync(0xffffffffu, ac, off);
            ao += __shfl_xor_sync(0xffffffffu, ao, off);
        }

        if (l == 0) {
            float f_ = fast_sigmoid(af + gxf);
            float i_ = fast_sigmoid(ai + gxi);
            float cd = __tanhf(ac + gxc);
            float o_ = fast_sigmoid(ao + gxo);
            cst = f_ * cst + i_ * cd;
            float h_ = o_ * cst;                   // reference omits tanh(c)
            __stcg(&g_h[(size_t)(t + 1) * HH + unit], h_);

            // prefetch gx for next step (overlaps barrier + next dot)
            int tn = (t + 1 < TT) ? (t + 1) : t;
            gxf = __ldcg(&g_gx[0][tn][unit]);
            gxi = __ldcg(&g_gx[1][tn][unit]);
            gxc = __ldcg(&g_gx[2][tn][unit]);
            gxo = __ldcg(&g_gx[3][tn][unit]);
        }

        // ---- grid barrier (r10 exact: release RED + relaxed polls + confirm) ----
        __syncthreads();                           // CTA h stores done
        if (threadIdx.x == 0) {
            asm volatile("red.release.gpu.global.add.u32 [%0], %1;"
                         :: "l"(&g_bar), "r"(1u) : "memory");
            unsigned tgt = (unsigned)(t + 1) * (unsigned)REC_GRID;
            unsigned v;
            do {
                asm volatile("ld.relaxed.gpu.global.u32 %0, [%1];"
                             : "=r"(v) : "l"(&g_bar) : "memory");
            } while (v < tgt);
            asm volatile("ld.acquire.gpu.global.u32 %0, [%1];"
                         : "=r"(v) : "l"(&g_bar) : "memory");
        }
        __syncthreads();
    }
}

// ---------------------------------------------------------------------------
extern "C" void kernel_launch(void* const* d_in, const int* in_sizes, int n_in,
                              void* d_out, int out_size)
{
    const float* x   = (const float*)d_in[0];
    const float* Wxf = (const float*)d_in[1];
    const float* Whf = (const float*)d_in[2];
    const float* bf  = (const float*)d_in[3];
    const float* Wxi = (const float*)d_in[4];
    const float* Whi = (const float*)d_in[5];
    const float* bi  = (const float*)d_in[6];
    const float* Wxc = (const float*)d_in[7];
    const float* Whc = (const float*)d_in[8];
    const float* bc  = (const float*)d_in[9];
    const float* Wxo = (const float*)d_in[10];
    const float* Who = (const float*)d_in[11];
    const float* bo  = (const float*)d_in[12];
    const float* Wy  = (const float*)d_in[13];
    const float* by  = (const float*)d_in[14];
    float* y = (float*)d_out;

    void* p_gx = nullptr;
    void* p_h  = nullptr;
    cudaGetSymbolAddress(&p_gx, g_gx);
    cudaGetSymbolAddress(&p_h,  g_h);
    float* gx = (float*)p_gx;
    float* hbuf = (float*)p_h;

    init_kernel<<<4, 256>>>();

    // Input projections: 4 GEMMs [4096,1024] = x[4096,512] @ Wx^T + b
    dim3 g1(HH / 64, TT / 64);
    gemm_tn_bias<<<g1, 256>>>(x, Wxf, bf, gx + 0 * (size_t)TT * HH, TT, HH, II);
    gemm_tn_bias<<<g1, 256>>>(x, Wxi, bi, gx + 1 * (size_t)TT * HH, TT, HH, II);
    gemm_tn_bias<<<g1, 256>>>(x, Wxc, bc, gx + 2 * (size_t)TT * HH, TT, HH, II);
    gemm_tn_bias<<<g1, 256>>>(x, Wxo, bo, gx + 3 * (size_t)TT * HH, TT, HH, II);

    // Sequential recurrence (persistent, weights in registers)
    lstm_rec<<<REC_GRID, REC_THREADS>>>(Whf, Whi, Whc, Who);

    // Output projection: y[4096,256] = hs[4096,1024] @ Wy^T + by
    dim3 g2(OO / 64, TT / 64);
    gemm_tn_bias<<<g2, 256>>>(hbuf + HH, Wy, by, y, TT, OO, HH);
}

// round 13
// speedup vs baseline: 1.2003x; 1.1714x over previous
#include <cuda_runtime.h>
#include <math.h>

#define TT 4096
#define II 512
#define HH 1024
#define OO 256

#define REC_GRID 128
#define REC_THREADS 256   // 8 warps; warp w owns hidden unit blockIdx.x*8+w
#define UNITS_PER_CTA 8

// Scratch (allocation-free: __device__ globals)
__device__ float g_gx[4][TT][HH];        // per-gate input projections
__device__ float g_h[(TT + 1) * HH];     // row 0 = h_{-1} = 0, row t+1 = h_t
__device__ unsigned g_bar;               // grid barrier counter (monotonic per launch)

// ---------------------------------------------------------------------------
__global__ void init_kernel() {
    int i = blockIdx.x * blockDim.x + threadIdx.x;
    if (i < HH) g_h[i] = 0.0f;
    if (i == 0) g_bar = 0u;
}

// ---------------------------------------------------------------------------
// C[M,N] = A[M,K] @ B[N,K]^T + bias[N]   (both A and B are K-contiguous)
// ---------------------------------------------------------------------------
__global__ __launch_bounds__(256) void gemm_tn_bias(
    const float* __restrict__ A, const float* __restrict__ B,
    const float* __restrict__ bias, float* __restrict__ C,
    int M, int N, int K)
{
    __shared__ float As[16][68];
    __shared__ float Bs[16][68];

    const int bm = blockIdx.y * 64;
    const int bn = blockIdx.x * 64;
    const int tid = threadIdx.x;

    const int lr = tid >> 2;
    const int lk = (tid & 3) << 2;
    const int tx = tid & 15;
    const int ty = tid >> 4;

    float acc[4][4] = {};

    for (int k0 = 0; k0 < K; k0 += 16) {
        float4 av = *(const float4*)(A + (size_t)(bm + lr) * K + k0 + lk);
        float4 bv = *(const float4*)(B + (size_t)(bn + lr) * K + k0 + lk);
        __syncthreads();
        As[lk + 0][lr] = av.x; As[lk + 1][lr] = av.y;
        As[lk + 2][lr] = av.z; As[lk + 3][lr] = av.w;
        Bs[lk + 0][lr] = bv.x; Bs[lk + 1][lr] = bv.y;
        Bs[lk + 2][lr] = bv.z; Bs[lk + 3][lr] = bv.w;
        __syncthreads();
#pragma unroll
        for (int kk = 0; kk < 16; kk++) {
            float4 af = *(const float4*)&As[kk][ty * 4];
            float4 bf = *(const float4*)&Bs[kk][tx * 4];
            float am[4] = {af.x, af.y, af.z, af.w};
            float bn_[4] = {bf.x, bf.y, bf.z, bf.w};
#pragma unroll
            for (int i = 0; i < 4; i++)
#pragma unroll
                for (int j = 0; j < 4; j++)
                    acc[i][j] += am[i] * bn_[j];
        }
    }

    const int row = bm + ty * 4;
    const int col = bn + tx * 4;
    float b0 = bias[col + 0], b1 = bias[col + 1], b2 = bias[col + 2], b3 = bias[col + 3];
#pragma unroll
    for (int i = 0; i < 4; i++) {
        float4 out;
        out.x = acc[i][0] + b0;
        out.y = acc[i][1] + b1;
        out.z = acc[i][2] + b2;
        out.w = acc[i][3] + b3;
        *(float4*)&C[(size_t)(row + i) * N + col] = out;
    }
}

__device__ __forceinline__ float fast_sigmoid(float x) {
    return 0.5f * __tanhf(0.5f * x) + 0.5f;   // one MUFU, no divide
}

// ---------------------------------------------------------------------------
// Persistent recurrence. 128 CTAs, 8 warps each; warp w owns unit b*8+w.
// NEW: h row staged through SMEM — ONE LDG.128 per lane per step (warp w
// fetches segment w), then all warps dot from SMEM. L2 read traffic per step
// drops 8x (4MB -> 512KB), removing ~650 cyc/step of chip-wide LTS pressure.
// Barrier: r10's (release-RED + relaxed polls), confirm-acquire dropped —
// with .cg loads (L1 bypassed) the release-RED already guarantees h data is
// L2-visible before the counter increment is.
// ---------------------------------------------------------------------------
__global__ __launch_bounds__(REC_THREADS, 1) void lstm_rec(
    const float* __restrict__ Whf, const float* __restrict__ Whi,
    const float* __restrict__ Whc, const float* __restrict__ Who)
{
    const int w = threadIdx.x >> 5;
    const int l = threadIdx.x & 31;
    const int unit = blockIdx.x * UNITS_PER_CTA + w;

    __shared__ __align__(16) float sh_h[HH];

    // Recurrent weights into registers (once). Lane l chunk i: h[l*4+128*i ..+4)
    float4 wf[8], wi[8], wc[8], wo[8];
    {
        const float* rf = Whf + (size_t)unit * HH;
        const float* ri = Whi + (size_t)unit * HH;
        const float* rc = Whc + (size_t)unit * HH;
        const float* ro = Who + (size_t)unit * HH;
#pragma unroll
        for (int i = 0; i < 8; i++) {
            int c = l * 4 + 128 * i;
            wf[i] = *(const float4*)(rf + c);
            wi[i] = *(const float4*)(ri + c);
            wc[i] = *(const float4*)(rc + c);
            wo[i] = *(const float4*)(ro + c);
        }
    }

    float cst = 0.0f;  // cell state (lane 0)

    // Prefetch gx for t=0
    float gxf = 0.f, gxi = 0.f, gxc = 0.f, gxo = 0.f;
    if (l == 0) {
        gxf = __ldcg(&g_gx[0][0][unit]);
        gxi = __ldcg(&g_gx[1][0][unit]);
        gxc = __ldcg(&g_gx[2][0][unit]);
        gxo = __ldcg(&g_gx[3][0][unit]);
    }

    const int seg = w * 128 + l * 4;   // this thread's 16B of the h row

    for (int t = 0; t < TT; t++) {
        // ---- cooperative fetch: CTA loads row t ONCE into smem ----
        {
            float4 hv = __ldcg((const float4*)(g_h + (size_t)t * HH + seg));
            *(float4*)&sh_h[seg] = hv;
        }
        __syncthreads();

        float af = 0.f, ai = 0.f, ac = 0.f, ao = 0.f;
#pragma unroll
        for (int i = 0; i < 8; i++) {
            float4 hv = *(const float4*)&sh_h[l * 4 + 128 * i];
            af += wf[i].x * hv.x; ai += wi[i].x * hv.x; ac += wc[i].x * hv.x; ao += wo[i].x * hv.x;
            af += wf[i].y * hv.y; ai += wi[i].y * hv.y; ac += wc[i].y * hv.y; ao += wo[i].y * hv.y;
            af += wf[i].z * hv.z; ai += wi[i].z * hv.z; ac += wc[i].z * hv.z; ao += wo[i].z * hv.z;
            af += wf[i].w * hv.w; ai += wi[i].w * hv.w; ac += wc[i].w * hv.w; ao += wo[i].w * hv.w;
        }
#pragma unroll
        for (int off = 16; off > 0; off >>= 1) {
            af += __shfl_xor_sync(0xffffffffu, af, off);
            ai += __shfl_xor_sync(0xffffffffu, ai, off);
            ac += __shfl_xor_sync(0xffffffffu, ac, off);
            ao += __shfl_xor_sync(0xffffffffu, ao, off);
        }

        if (l == 0) {
            float f_ = fast_sigmoid(af + gxf);
            float i_ = fast_sigmoid(ai + gxi);
            float cd = __tanhf(ac + gxc);
            float o_ = fast_sigmoid(ao + gxo);
            cst = f_ * cst + i_ * cd;
            float h_ = o_ * cst;                   // reference omits tanh(c)
            __stcg(&g_h[(size_t)(t + 1) * HH + unit], h_);

            // prefetch gx for next step (overlaps barrier + next dot)
            int tn = (t + 1 < TT) ? (t + 1) : t;
            gxf = __ldcg(&g_gx[0][tn][unit]);
            gxi = __ldcg(&g_gx[1][tn][unit]);
            gxc = __ldcg(&g_gx[2][tn][unit]);
            gxo = __ldcg(&g_gx[3][tn][unit]);
        }

        // ---- grid barrier: release RED + relaxed polls (no confirm trip) ----
        __syncthreads();                           // CTA h stores done
        if (threadIdx.x == 0) {
            asm volatile("red.release.gpu.global.add.u32 [%0], %1;"
                         :: "l"(&g_bar), "r"(1u) : "memory");
            unsigned tgt = (unsigned)(t + 1) * (unsigned)REC_GRID;
            unsigned v;
            do {
                asm volatile("ld.relaxed.gpu.global.u32 %0, [%1];"
                             : "=r"(v) : "l"(&g_bar) : "memory");
            } while (v < tgt);
        }
        __syncthreads();
    }
}

// ---------------------------------------------------------------------------
extern "C" void kernel_launch(void* const* d_in, const int* in_sizes, int n_in,
                              void* d_out, int out_size)
{
    const float* x   = (const float*)d_in[0];
    const float* Wxf = (const float*)d_in[1];
    const float* Whf = (const float*)d_in[2];
    const float* bf  = (const float*)d_in[3];
    const float* Wxi = (const float*)d_in[4];
    const float* Whi = (const float*)d_in[5];
    const float* bi  = (const float*)d_in[6];
    const float* Wxc = (const float*)d_in[7];
    const float* Whc = (const float*)d_in[8];
    const float* bc  = (const float*)d_in[9];
    const float* Wxo = (const float*)d_in[10];
    const float* Who = (const float*)d_in[11];
    const float* bo  = (const float*)d_in[12];
    const float* Wy  = (const float*)d_in[13];
    const float* by  = (const float*)d_in[14];
    float* y = (float*)d_out;

    void* p_gx = nullptr;
    void* p_h  = nullptr;
    cudaGetSymbolAddress(&p_gx, g_gx);
    cudaGetSymbolAddress(&p_h,  g_h);
    float* gx = (float*)p_gx;
    float* hbuf = (float*)p_h;

    init_kernel<<<4, 256>>>();

    // Input projections: 4 GEMMs [4096,1024] = x[4096,512] @ Wx^T + b
    dim3 g1(HH / 64, TT / 64);
    gemm_tn_bias<<<g1, 256>>>(x, Wxf, bf, gx + 0 * (size_t)TT * HH, TT, HH, II);
    gemm_tn_bias<<<g1, 256>>>(x, Wxi, bi, gx + 1 * (size_t)TT * HH, TT, HH, II);
    gemm_tn_bias<<<g1, 256>>>(x, Wxc, bc, gx + 2 * (size_t)TT * HH, TT, HH, II);
    gemm_tn_bias<<<g1, 256>>>(x, Wxo, bo, gx + 3 * (size_t)TT * HH, TT, HH, II);

    // Sequential recurrence (persistent, weights in registers)
    lstm_rec<<<REC_GRID, REC_THREADS>>>(Whf, Whi, Whc, Who);

    // Output projection: y[4096,256] = hs[4096,1024] @ Wy^T + by
    dim3 g2(OO / 64, TT / 64);
    gemm_tn_bias<<<g2, 256>>>(hbuf + HH, Wy, by, y, TT, OO, HH);
}